// round 1
// baseline (speedup 1.0000x reference)
#include <cuda_runtime.h>

#define NN 50000
#define NE 800000
#define HID 128
#define HEADS 4
#define HD 512  // HEADS*HID
#define NEG 0.2f

// ---------------- scratch (device globals; no allocation allowed) ----------------
__device__ float g_h[(size_t)NN * HD];        // [N, H*C] post-GEMM features
__device__ float g_asrc[NN * HEADS];
__device__ float g_adst[NN * HEADS];
__device__ float g_den[NN * HEADS];
__device__ float g_ew[(size_t)NE * HEADS];    // per sorted edge, per head softmax numerator
__device__ float g_conv[(size_t)NN * HID];    // GAT layer output (head-mean + bias)
__device__ float g_tmp[(size_t)NN * HID];     // layer-0 output features
__device__ int   g_rowptr[NN + 1];
__device__ int   g_deg[NN];                   // histogram, then reused as cursor
__device__ int   g_srcs[NE];                  // src node of each dst-sorted edge
__device__ int   g_is64;

// ---------------- edge dtype detection (int64 vs demoted int32) ----------------
__global__ void k_detect(const unsigned int* p) {
    __shared__ unsigned int acc;
    if (threadIdx.x == 0) acc = 0u;
    __syncthreads();
    unsigned int v = 0u;
    for (int i = threadIdx.x; i < 4096; i += 256) v |= p[2 * i + 1];
    atomicOr(&acc, v);
    __syncthreads();
    if (threadIdx.x == 0) g_is64 = (acc == 0u) ? 1 : 0;
}

__device__ __forceinline__ int edge_val(const void* ei, int idx) {
    if (g_is64) return (int)((const long long*)ei)[idx];
    return ((const int*)ei)[idx];
}

// ---------------- CSR build ----------------
__global__ void k_zero_deg() {
    int i = blockIdx.x * blockDim.x + threadIdx.x;
    if (i < NN) g_deg[i] = 0;
}

__global__ void k_degree(const void* ei) {
    int e = blockIdx.x * blockDim.x + threadIdx.x;
    if (e >= NE) return;
    int d = edge_val(ei, NE + e);
    atomicAdd(&g_deg[d], 1);
}

__global__ void k_scan() {
    __shared__ int sh[1024];
    __shared__ int carry;
    int t = threadIdx.x;
    if (t == 0) carry = 0;
    __syncthreads();
    for (int base = 0; base < NN; base += 1024) {
        int v = (base + t < NN) ? g_deg[base + t] : 0;
        sh[t] = v;
        __syncthreads();
        for (int off = 1; off < 1024; off <<= 1) {
            int x = (t >= off) ? sh[t - off] : 0;
            __syncthreads();
            sh[t] += x;
            __syncthreads();
        }
        int incl = sh[t];
        int total = sh[1023];
        if (base + t < NN) {
            g_rowptr[base + t] = carry + (incl - v);
            g_deg[base + t] = 0;   // reset for bucket cursor
        }
        __syncthreads();
        if (t == 0) carry += total;
        __syncthreads();
    }
    if (t == 0) g_rowptr[NN] = carry;
}

__global__ void k_bucket(const void* ei) {
    int e = blockIdx.x * blockDim.x + threadIdx.x;
    if (e >= NE) return;
    int s = edge_val(ei, e);
    int d = edge_val(ei, NE + e);
    int pos = atomicAdd(&g_deg[d], 1);
    g_srcs[g_rowptr[d] + pos] = s;
}

// ---------------- generic fp32 GEMM: C = op(A[M,128]) @ B[128,Ncols] (+bias)(+C) ----------------
template <bool RELU, bool ACC>
__global__ __launch_bounds__(256) void k_gemm(
    const float* __restrict__ A, const float* __restrict__ B,
    float* __restrict__ C, const float* __restrict__ bias,
    int M, int Ncols)
{
    __shared__ float As[16][132];  // transposed A tile, padded
    __shared__ float Bs[16][128];
    int bm = blockIdx.y * 128, bn = blockIdx.x * 128;
    int t = threadIdx.x;
    int tx = t & 15, ty = t >> 4;
    float acc[8][8];
#pragma unroll
    for (int i = 0; i < 8; i++)
#pragma unroll
        for (int j = 0; j < 8; j++) acc[i][j] = 0.f;

    for (int k0 = 0; k0 < HID; k0 += 16) {
#pragma unroll
        for (int i = 0; i < 8; i++) {
            int lin = t + i * 256;
            int m = lin >> 4, k = lin & 15;
            float v = 0.f;
            if (bm + m < M) v = A[(size_t)(bm + m) * HID + k0 + k];
            if (RELU) v = fmaxf(v, 0.f);
            As[k][m] = v;
        }
#pragma unroll
        for (int i = 0; i < 8; i++) {
            int lin = t + i * 256;
            int k = lin >> 7, n = lin & 127;
            Bs[k][n] = B[(size_t)(k0 + k) * Ncols + bn + n];
        }
        __syncthreads();
#pragma unroll
        for (int k = 0; k < 16; k++) {
            float4 a0 = *(const float4*)&As[k][ty * 8];
            float4 a1 = *(const float4*)&As[k][ty * 8 + 4];
            float4 b0 = *(const float4*)&Bs[k][tx * 8];
            float4 b1 = *(const float4*)&Bs[k][tx * 8 + 4];
            float a[8] = {a0.x, a0.y, a0.z, a0.w, a1.x, a1.y, a1.z, a1.w};
            float b[8] = {b0.x, b0.y, b0.z, b0.w, b1.x, b1.y, b1.z, b1.w};
#pragma unroll
            for (int i = 0; i < 8; i++)
#pragma unroll
                for (int j = 0; j < 8; j++)
                    acc[i][j] = fmaf(a[i], b[j], acc[i][j]);
        }
        __syncthreads();
    }
#pragma unroll
    for (int i = 0; i < 8; i++) {
        int m = bm + ty * 8 + i;
        if (m >= M) continue;
        float* crow = C + (size_t)m * Ncols + bn + tx * 8;
#pragma unroll
        for (int j = 0; j < 8; j += 4) {
            float4 r;
            r.x = acc[i][j]; r.y = acc[i][j + 1]; r.z = acc[i][j + 2]; r.w = acc[i][j + 3];
            if (bias) {
                float4 bb = *(const float4*)(bias + bn + tx * 8 + j);
                r.x += bb.x; r.y += bb.y; r.z += bb.z; r.w += bb.w;
            }
            if (ACC) {
                float4 c0 = *(const float4*)(crow + j);
                r.x += c0.x; r.y += c0.y; r.z += c0.z; r.w += c0.w;
            }
            *(float4*)(crow + j) = r;
        }
    }
}

// ---------------- attention logits: asrc/adst per (node, head) ----------------
__global__ void k_alpha(const float* __restrict__ ws, const float* __restrict__ wd) {
    int n = (blockIdx.x * blockDim.x + threadIdx.x) >> 5;
    if (n >= NN) return;
    int lane = threadIdx.x & 31;
    const float* hrow = g_h + (size_t)n * HD;
#pragma unroll
    for (int h = 0; h < HEADS; h++) {
        float4 hv = *(const float4*)(hrow + h * HID + lane * 4);
        float4 s4 = *(const float4*)(ws + h * HID + lane * 4);
        float4 d4 = *(const float4*)(wd + h * HID + lane * 4);
        float s1 = hv.x * s4.x + hv.y * s4.y + hv.z * s4.z + hv.w * s4.w;
        float s2 = hv.x * d4.x + hv.y * d4.y + hv.z * d4.z + hv.w * d4.w;
#pragma unroll
        for (int off = 16; off; off >>= 1) {
            s1 += __shfl_xor_sync(0xffffffffu, s1, off);
            s2 += __shfl_xor_sync(0xffffffffu, s2, off);
        }
        if (lane == 0) {
            g_asrc[n * HEADS + h] = s1;
            g_adst[n * HEADS + h] = s2;
        }
    }
}

__device__ __forceinline__ float leaky(float a) { return a >= 0.f ? a : NEG * a; }

// ---------------- per-node softmax: max, exp weights, denom (warp per node) ----------------
__global__ void k_soft() {
    int n = (blockIdx.x * blockDim.x + threadIdx.x) >> 5;
    if (n >= NN) return;
    int lane = threadIdx.x & 31;
    int b = g_rowptr[n], e = g_rowptr[n + 1];
    float4 ad = *(const float4*)(g_adst + n * 4);
    float m0 = -3.4e38f, m1 = m0, m2 = m0, m3 = m0;
    for (int i = b + lane; i < e; i += 32) {
        int s = g_srcs[i];
        float4 as = *(const float4*)(g_asrc + s * 4);
        m0 = fmaxf(m0, leaky(as.x + ad.x));
        m1 = fmaxf(m1, leaky(as.y + ad.y));
        m2 = fmaxf(m2, leaky(as.z + ad.z));
        m3 = fmaxf(m3, leaky(as.w + ad.w));
    }
#pragma unroll
    for (int off = 16; off; off >>= 1) {
        m0 = fmaxf(m0, __shfl_xor_sync(0xffffffffu, m0, off));
        m1 = fmaxf(m1, __shfl_xor_sync(0xffffffffu, m1, off));
        m2 = fmaxf(m2, __shfl_xor_sync(0xffffffffu, m2, off));
        m3 = fmaxf(m3, __shfl_xor_sync(0xffffffffu, m3, off));
    }
    float d0 = 0.f, d1 = 0.f, d2 = 0.f, d3 = 0.f;
    for (int i = b + lane; i < e; i += 32) {
        int s = g_srcs[i];
        float4 as = *(const float4*)(g_asrc + s * 4);
        float4 w;
        w.x = __expf(leaky(as.x + ad.x) - m0); d0 += w.x;
        w.y = __expf(leaky(as.y + ad.y) - m1); d1 += w.y;
        w.z = __expf(leaky(as.z + ad.z) - m2); d2 += w.z;
        w.w = __expf(leaky(as.w + ad.w) - m3); d3 += w.w;
        *(float4*)(g_ew + (size_t)i * 4) = w;
    }
#pragma unroll
    for (int off = 16; off; off >>= 1) {
        d0 += __shfl_xor_sync(0xffffffffu, d0, off);
        d1 += __shfl_xor_sync(0xffffffffu, d1, off);
        d2 += __shfl_xor_sync(0xffffffffu, d2, off);
        d3 += __shfl_xor_sync(0xffffffffu, d3, off);
    }
    if (lane == 0) {
        float4 dv = {d0, d1, d2, d3};
        *(float4*)(g_den + n * 4) = dv;
    }
}

// ---------------- aggregation: warp per node, lane l owns channels l*4..l*4+3 of each head ----------------
__global__ void k_aggr(const float* __restrict__ cb) {
    int n = (blockIdx.x * blockDim.x + threadIdx.x) >> 5;
    if (n >= NN) return;
    int lane = threadIdx.x & 31;
    int b = g_rowptr[n], e = g_rowptr[n + 1];
    float4 den = *(const float4*)(g_den + n * 4);
    float i0 = 1.f / (den.x + 1e-16f);
    float i1 = 1.f / (den.y + 1e-16f);
    float i2 = 1.f / (den.z + 1e-16f);
    float i3 = 1.f / (den.w + 1e-16f);
    float4 a0 = {0, 0, 0, 0}, a1 = a0, a2 = a0, a3 = a0;
    for (int i = b; i < e; i++) {
        int s = g_srcs[i];                               // warp-uniform
        float4 w = *(const float4*)(g_ew + (size_t)i * 4); // warp-uniform
        const float4* hp = (const float4*)(g_h + (size_t)s * HD) + lane;
        float4 h0 = hp[0], h1 = hp[32], h2 = hp[64], h3 = hp[96];
        a0.x = fmaf(w.x, h0.x, a0.x); a0.y = fmaf(w.x, h0.y, a0.y);
        a0.z = fmaf(w.x, h0.z, a0.z); a0.w = fmaf(w.x, h0.w, a0.w);
        a1.x = fmaf(w.y, h1.x, a1.x); a1.y = fmaf(w.y, h1.y, a1.y);
        a1.z = fmaf(w.y, h1.z, a1.z); a1.w = fmaf(w.y, h1.w, a1.w);
        a2.x = fmaf(w.z, h2.x, a2.x); a2.y = fmaf(w.z, h2.y, a2.y);
        a2.z = fmaf(w.z, h2.z, a2.z); a2.w = fmaf(w.z, h2.w, a2.w);
        a3.x = fmaf(w.w, h3.x, a3.x); a3.y = fmaf(w.w, h3.y, a3.y);
        a3.z = fmaf(w.w, h3.z, a3.z); a3.w = fmaf(w.w, h3.w, a3.w);
    }
    float4 bias = *(const float4*)(cb + lane * 4);
    float4 o;
    o.x = 0.25f * (a0.x * i0 + a1.x * i1 + a2.x * i2 + a3.x * i3) + bias.x;
    o.y = 0.25f * (a0.y * i0 + a1.y * i1 + a2.y * i2 + a3.y * i3) + bias.y;
    o.z = 0.25f * (a0.z * i0 + a1.z * i1 + a2.z * i2 + a3.z * i3) + bias.z;
    o.w = 0.25f * (a0.w * i0 + a1.w * i1 + a2.w * i2 + a3.w * i3) + bias.w;
    *(float4*)(g_conv + (size_t)n * HID + lane * 4) = o;
}

// ---------------- host orchestration ----------------
extern "C" void kernel_launch(void* const* d_in, const int* in_sizes, int n_in,
                              void* d_out, int out_size) {
    const float* x       = (const float*)d_in[0];
    const void*  ei      = d_in[1];
    const float* conv_w  = (const float*)d_in[2];
    const float* att_src = (const float*)d_in[3];
    const float* att_dst = (const float*)d_in[4];
    const float* conv_b  = (const float*)d_in[5];
    const float* proj_w  = (const float*)d_in[6];
    const float* proj_b  = (const float*)d_in[7];
    const float* skip_w  = (const float*)d_in[8];
    const float* skip_b  = (const float*)d_in[9];
    float* out = (float*)d_out;

    float *p_h, *p_conv, *p_tmp;
    cudaGetSymbolAddress((void**)&p_h, g_h);
    cudaGetSymbolAddress((void**)&p_conv, g_conv);
    cudaGetSymbolAddress((void**)&p_tmp, g_tmp);

    // CSR build (once per call; reused by both layers)
    k_detect<<<1, 256>>>((const unsigned int*)ei);
    k_zero_deg<<<(NN + 255) / 256, 256>>>();
    k_degree<<<(NE + 255) / 256, 256>>>(ei);
    k_scan<<<1, 1024>>>();
    k_bucket<<<(NE + 255) / 256, 256>>>(ei);

    const float* feat = x;
    const int NWB = (NN + 7) / 8;  // warp-per-node blocks at 256 threads
    for (int l = 0; l < 2; l++) {
        float* lout = (l == 0) ? p_tmp : out;
        dim3 gh(HD / 128, (NN + 127) / 128);
        k_gemm<false, false><<<gh, 256>>>(feat, conv_w + (size_t)l * HID * HD,
                                          p_h, nullptr, NN, HD);
        k_alpha<<<NWB, 256>>>(att_src + l * HEADS * HID, att_dst + l * HEADS * HID);
        k_soft<<<NWB, 256>>>();
        k_aggr<<<NWB, 256>>>(conv_b + l * HID);
        dim3 go(1, (NN + 127) / 128);
        k_gemm<true, false><<<go, 256>>>(p_conv, proj_w + (size_t)l * HID * HID,
                                         lout, proj_b + l * HID, NN, HID);
        k_gemm<false, true><<<go, 256>>>(feat, skip_w + (size_t)l * HID * HID,
                                         lout, skip_b + l * HID, NN, HID);
        feat = p_tmp;
    }
}

// round 8
// speedup vs baseline: 2.6376x; 2.6376x over previous
#include <cuda_runtime.h>
#include <cuda_bf16.h>
#include <cstdint>

#define NN 50000
#define NE 800000
#define HID 128
#define HEADS 4
#define HD 512  // HEADS*HID
#define NEG 0.2f
#define NBLK ((NN + 255) / 256)

// ---------------- scratch (device globals; no allocation allowed) ----------------
__device__ float g_h[(size_t)NN * HD];        // [N, H*C] post-GEMM features
__device__ float g_asrc[NN * HEADS];
__device__ float g_adst[NN * HEADS];
__device__ float g_den[NN * HEADS];
__device__ float g_ew[(size_t)NE * HEADS];    // per sorted edge, per head softmax numerator
__device__ float g_conv[(size_t)NN * HID];    // GAT layer output (head-mean + bias)
__device__ float g_tmp[(size_t)NN * HID];     // layer-0 output features
__device__ int   g_rowptr[NN + 1];
__device__ int   g_deg[NN];                   // histogram, then reused as cursor
__device__ int   g_srcs[NE];                  // src node of each dst-sorted edge
__device__ int   g_bsum[NBLK];
__device__ int   g_is64;
// transposed + bf16-split weights: per layer 768 rows (512 conv | 128 proj | 128 skip) x 128 k
__device__ __nv_bfloat16 g_wth[2 * 768 * 128];
__device__ __nv_bfloat16 g_wtl[2 * 768 * 128];

__device__ __forceinline__ uint32_t smem_u32(const void* p) {
    uint32_t a;
    asm("{ .reg .u64 t; cvta.to.shared.u64 t, %1; cvt.u32.u64 %0, t; }" : "=r"(a) : "l"(p));
    return a;
}

#define LDM_X4(r0, r1, r2, r3, addr) \
    asm volatile("ldmatrix.sync.aligned.m8n8.x4.shared.b16 {%0,%1,%2,%3}, [%4];" \
        : "=r"(r0), "=r"(r1), "=r"(r2), "=r"(r3) : "r"(addr))

#define MMA_BF16(c, a, b) \
    asm volatile("mma.sync.aligned.m16n8k16.row.col.f32.bf16.bf16.f32 " \
        "{%0,%1,%2,%3}, {%4,%5,%6,%7}, {%8,%9}, {%0,%1,%2,%3};" \
        : "+f"((c)[0]), "+f"((c)[1]), "+f"((c)[2]), "+f"((c)[3]) \
        : "r"((a)[0]), "r"((a)[1]), "r"((a)[2]), "r"((a)[3]), "r"((b)[0]), "r"((b)[1]))

// ---------------- edge dtype detection (int64 vs demoted int32) ----------------
__global__ void k_detect(const unsigned int* p) {
    __shared__ unsigned int acc;
    if (threadIdx.x == 0) acc = 0u;
    __syncthreads();
    unsigned int v = 0u;
    for (int i = threadIdx.x; i < 4096; i += 256) v |= p[2 * i + 1];
    atomicOr(&acc, v);
    __syncthreads();
    if (threadIdx.x == 0) g_is64 = (acc == 0u) ? 1 : 0;
}
__device__ __forceinline__ int edge_val(const void* ei, int idx) {
    if (g_is64) return (int)((const long long*)ei)[idx];
    return ((const int*)ei)[idx];
}

// ---------------- CSR build ----------------
__global__ void k_zero_deg() {
    int i = blockIdx.x * blockDim.x + threadIdx.x;
    if (i < NN) g_deg[i] = 0;
}
__global__ void k_degree(const void* ei) {
    int e = blockIdx.x * blockDim.x + threadIdx.x;
    if (e >= NE) return;
    atomicAdd(&g_deg[edge_val(ei, NE + e)], 1);
}
__device__ __forceinline__ int warp_incl_scan(int x, int lane) {
#pragma unroll
    for (int o = 1; o < 32; o <<= 1) {
        int y = __shfl_up_sync(0xffffffffu, x, o);
        if (lane >= o) x += y;
    }
    return x;
}
__global__ void k_scan1() {
    int b = blockIdx.x, t = threadIdx.x, i = b * 256 + t;
    int lane = t & 31, w = t >> 5;
    int v = (i < NN) ? g_deg[i] : 0;
    int x = warp_incl_scan(v, lane);
    __shared__ int ws[8];
    if (lane == 31) ws[w] = x;
    __syncthreads();
    int add = 0;
#pragma unroll
    for (int j = 0; j < 8; j++) if (j < w) add += ws[j];
    int incl = x + add;
    if (i < NN) g_rowptr[i] = incl - v;
    if (t == 255) g_bsum[b] = incl;
}
__global__ void k_scan2() {
    int t = threadIdx.x, lane = t & 31, w = t >> 5;
    int v = (t < NBLK) ? g_bsum[t] : 0;
    int x = warp_incl_scan(v, lane);
    __shared__ int ws[8];
    if (lane == 31) ws[w] = x;
    __syncthreads();
    int add = 0;
#pragma unroll
    for (int j = 0; j < 8; j++) if (j < w) add += ws[j];
    if (t < NBLK) g_bsum[t] = x + add - v;
}
__global__ void k_scan3() {
    int i = blockIdx.x * blockDim.x + threadIdx.x;
    if (i < NN) { g_rowptr[i] += g_bsum[i >> 8]; g_deg[i] = 0; }
    if (i == 0) g_rowptr[NN] = NE;
}
__global__ void k_bucket(const void* ei) {
    int e = blockIdx.x * blockDim.x + threadIdx.x;
    if (e >= NE) return;
    int s = edge_val(ei, e);
    int d = edge_val(ei, NE + e);
    int pos = atomicAdd(&g_deg[d], 1);
    g_srcs[g_rowptr[d] + pos] = s;
}

// ---------------- weight transpose + bf16 hi/lo split ----------------
__global__ void k_wsplit(const float* __restrict__ conv_w, const float* __restrict__ proj_w,
                         const float* __restrict__ skip_w) {
    int i = blockIdx.x * 256 + threadIdx.x;
    if (i >= 2 * 768 * 128) return;
    int l = i / 98304, r = i % 98304;
    int row = r >> 7, k = r & 127;
    float v;
    if (row < 512)       v = conv_w[l * 65536 + k * 512 + row];
    else if (row < 640)  v = proj_w[l * 16384 + k * 128 + (row - 512)];
    else                 v = skip_w[l * 16384 + k * 128 + (row - 640)];
    __nv_bfloat16 hi = __float2bfloat16(v);
    __nv_bfloat16 lo = __float2bfloat16(v - __bfloat162float(hi));
    g_wth[i] = hi;
    g_wtl[i] = lo;
}

// ================= HMMA split-bf16 GEMM =================
// smem layout: bias 0, att_s 1024, att_d 1536, s1 2048, s2 2560, tiles from 3072
#define TILE_STRIDE 272            // (128+8) bf16 per row
#define TILE_BYTES  (128 * TILE_STRIDE)
#define SM_BIAS 0
#define SM_AS   1024
#define SM_AD   1536
#define SM_S1   2048
#define SM_S2   2560
#define SM_TILE 3072
#define SM_TOT  (SM_TILE + 4 * TILE_BYTES)   // 142336 B

__device__ __forceinline__ uint32_t pack_bf2(__nv_bfloat16 a, __nv_bfloat16 b) {
    return (uint32_t)__bfloat16_as_ushort(a) | ((uint32_t)__bfloat16_as_ushort(b) << 16);
}

// ATT: fuse per-head attention logits; NCHUNK: k-chunks (1=conv, 2=proj+skip fused);
// RELU0: relu on chunk-0 A operand.
template <bool ATT, int NCHUNK, bool RELU0>
__global__ __launch_bounds__(256, 1) void k_hmma(
    const float* __restrict__ A0, const float* __restrict__ A1,
    const __nv_bfloat16* __restrict__ Bh, const __nv_bfloat16* __restrict__ Bl,
    float* __restrict__ C, const float* __restrict__ bias, const float* __restrict__ bias2,
    int M, int ldc,
    const float* __restrict__ att_s, const float* __restrict__ att_d,
    float* __restrict__ asrc_out, float* __restrict__ adst_out)
{
    extern __shared__ char sm[];
    uint32_t smb = smem_u32(sm);
    const uint32_t uAh = smb + SM_TILE;
    const uint32_t uAl = uAh + TILE_BYTES;
    const uint32_t uBh = uAl + TILE_BYTES;
    const uint32_t uBl = uBh + TILE_BYTES;
    float* sBias = (float*)(sm + SM_BIAS);
    float* sAS   = (float*)(sm + SM_AS);
    float* sAD   = (float*)(sm + SM_AD);
    float* sS1   = (float*)(sm + SM_S1);
    float* sS2   = (float*)(sm + SM_S2);

    int t = threadIdx.x, lane = t & 31, wid = t >> 5;
    int bm = blockIdx.y * 128;
    int head = blockIdx.x;

    if (t < 128) {
        float bv = bias ? bias[t] : 0.f;
        if (bias2) bv += bias2[t];
        sBias[t] = bv;
        if (ATT) {
            sAS[t] = att_s[head * 128 + t];
            sAD[t] = att_d[head * 128 + t];
            sS1[t] = 0.f;
            sS2[t] = 0.f;
        }
    }

    int wm = (wid >> 2) * 64, wn = (wid & 3) * 32;
    // ldmatrix per-lane source offsets (bytes)
    const uint32_t aOff = (uint32_t)((wm + (lane & 7) + (lane & 8)) * TILE_STRIDE + ((lane & 16) ? 16 : 0));
    const uint32_t bOff = (uint32_t)((wn + (lane & 7) + ((lane & 16) ? 8 : 0)) * TILE_STRIDE + ((lane & 8) ? 16 : 0));

    float c[4][4][4];
#pragma unroll
    for (int i = 0; i < 4; i++)
#pragma unroll
        for (int j = 0; j < 4; j++)
#pragma unroll
            for (int k = 0; k < 4; k++) c[i][j][k] = 0.f;

#pragma unroll
    for (int ch = 0; ch < NCHUNK; ch++) {
        const float* Asrc = (ch == 0) ? A0 : A1;
        const bool relu = RELU0 && (ch == 0);
        // ---- A: fp32 -> bf16 hi/lo split into smem ----
#pragma unroll
        for (int i = 0; i < 8; i++) {
            int idx = t + i * 256;
            int r = idx >> 4, kc = idx & 15;
            int m = bm + r;
            float4 v0, v1;
            if (m < M) {
                const float4* p = (const float4*)(Asrc + (size_t)m * HID + kc * 8);
                v0 = p[0]; v1 = p[1];
            } else {
                v0 = make_float4(0.f, 0.f, 0.f, 0.f); v1 = v0;
            }
            float f[8] = {v0.x, v0.y, v0.z, v0.w, v1.x, v1.y, v1.z, v1.w};
            if (relu) {
#pragma unroll
                for (int j = 0; j < 8; j++) f[j] = fmaxf(f[j], 0.f);
            }
            uint4 uh, ul;
            uint32_t* ph = (uint32_t*)&uh;
            uint32_t* pl = (uint32_t*)&ul;
#pragma unroll
            for (int j = 0; j < 4; j++) {
                float a = f[2 * j], b = f[2 * j + 1];
                __nv_bfloat16 ha = __float2bfloat16(a), hb = __float2bfloat16(b);
                __nv_bfloat16 la = __float2bfloat16(a - __bfloat162float(ha));
                __nv_bfloat16 lb = __float2bfloat16(b - __bfloat162float(hb));
                ph[j] = pack_bf2(ha, hb);
                pl[j] = pack_bf2(la, lb);
            }
            uint32_t off = (uint32_t)(r * TILE_STRIDE + kc * 16);
            *(uint4*)(sm + SM_TILE + off) = uh;
            *(uint4*)(sm + SM_TILE + TILE_BYTES + off) = ul;
        }
        // ---- B: bf16 hi/lo copy into smem ----
        {
            const __nv_bfloat16* bh = Bh + (size_t)(ATT ? head : ch) * 16384;
            const __nv_bfloat16* bl = Bl + (size_t)(ATT ? head : ch) * 16384;
#pragma unroll
            for (int i = 0; i < 8; i++) {
                int idx = t + i * 256;
                int r = idx >> 4, kc = idx & 15;
                uint4 vh = *(const uint4*)(bh + r * 128 + kc * 8);
                uint4 vl = *(const uint4*)(bl + r * 128 + kc * 8);
                uint32_t off = (uint32_t)(r * TILE_STRIDE + kc * 16);
                *(uint4*)(sm + SM_TILE + 2 * TILE_BYTES + off) = vh;
                *(uint4*)(sm + SM_TILE + 3 * TILE_BYTES + off) = vl;
            }
        }
        __syncthreads();

        // ---- 3 precision passes: Ah*Bh, Ah*Bl, Al*Bh ----
#pragma unroll
        for (int pass = 0; pass < 3; pass++) {
            uint32_t aBase = ((pass == 2) ? uAl : uAh) + aOff;
            uint32_t bBase = ((pass == 1) ? uBl : uBh) + bOff;
#pragma unroll
            for (int k0 = 0; k0 < 8; k0++) {
                uint32_t ka = aBase + k0 * 32;
                uint32_t kb = bBase + k0 * 32;
                uint32_t a[4][4], b[4][2];
#pragma unroll
                for (int mt = 0; mt < 4; mt++)
                    LDM_X4(a[mt][0], a[mt][1], a[mt][2], a[mt][3], ka + mt * 16 * TILE_STRIDE);
#pragma unroll
                for (int np = 0; np < 2; np++)
                    LDM_X4(b[2 * np][0], b[2 * np][1], b[2 * np + 1][0], b[2 * np + 1][1],
                           kb + np * 16 * TILE_STRIDE);
#pragma unroll
                for (int mt = 0; mt < 4; mt++)
#pragma unroll
                    for (int nt = 0; nt < 4; nt++)
                        MMA_BF16(c[mt][nt], a[mt], b[nt]);
            }
        }
        __syncthreads();  // protect smem reuse on next chunk
    }

    // ---- epilogue ----
    int g = lane >> 2, t2 = (lane & 3) * 2;
    int cbase = ATT ? head * 128 : 0;
#pragma unroll
    for (int mt = 0; mt < 4; mt++) {
        int r0 = wm + mt * 16 + g;          // local rows r0, r0+8
        int m0 = bm + r0, m1 = m0 + 8;
        float s1_0 = 0.f, s2_0 = 0.f, s1_1 = 0.f, s2_1 = 0.f;
#pragma unroll
        for (int nt = 0; nt < 4; nt++) {
            int col = wn + nt * 8 + t2;
            float v0 = c[mt][nt][0], v1 = c[mt][nt][1];
            float v2 = c[mt][nt][2], v3 = c[mt][nt][3];
            if (ATT) {
                float w0 = sAS[col], w1 = sAS[col + 1];
                float d0 = sAD[col], d1 = sAD[col + 1];
                s1_0 += v0 * w0 + v1 * w1;
                s2_0 += v0 * d0 + v1 * d1;
                s1_1 += v2 * w0 + v3 * w1;
                s2_1 += v2 * d0 + v3 * d1;
            }
            float bb0 = sBias[col], bb1 = sBias[col + 1];
            if (m0 < M) { float2 o = {v0 + bb0, v1 + bb1}; *(float2*)(C + (size_t)m0 * ldc + cbase + col) = o; }
            if (m1 < M) { float2 o = {v2 + bb0, v3 + bb1}; *(float2*)(C + (size_t)m1 * ldc + cbase + col) = o; }
        }
        if (ATT) {
#pragma unroll
            for (int o = 1; o < 4; o <<= 1) {
                s1_0 += __shfl_xor_sync(0xffffffffu, s1_0, o);
                s2_0 += __shfl_xor_sync(0xffffffffu, s2_0, o);
                s1_1 += __shfl_xor_sync(0xffffffffu, s1_1, o);
                s2_1 += __shfl_xor_sync(0xffffffffu, s2_1, o);
            }
            if ((lane & 3) == 0) {
                atomicAdd(&sS1[r0], s1_0);
                atomicAdd(&sS2[r0], s2_0);
                atomicAdd(&sS1[r0 + 8], s1_1);
                atomicAdd(&sS2[r0 + 8], s2_1);
            }
        }
    }
    if (ATT) {
        __syncthreads();
        if (t < 128 && bm + t < M) {
            asrc_out[(bm + t) * HEADS + head] = sS1[t];
            adst_out[(bm + t) * HEADS + head] = sS2[t];
        }
    }
}

__device__ __forceinline__ float leaky(float a) { return a >= 0.f ? a : NEG * a; }

// ---------------- per-node softmax: max, exp weights, denom (warp per node) ----------------
__global__ void k_soft() {
    int n = (blockIdx.x * blockDim.x + threadIdx.x) >> 5;
    if (n >= NN) return;
    int lane = threadIdx.x & 31;
    int b = g_rowptr[n], e = g_rowptr[n + 1];
    float4 ad = *(const float4*)(g_adst + n * 4);
    float m0 = -3.4e38f, m1 = m0, m2 = m0, m3 = m0;
    for (int i = b + lane; i < e; i += 32) {
        int s = g_srcs[i];
        float4 as = *(const float4*)(g_asrc + s * 4);
        m0 = fmaxf(m0, leaky(as.x + ad.x));
        m1 = fmaxf(m1, leaky(as.y + ad.y));
        m2 = fmaxf(m2, leaky(as.z + ad.z));
        m3 = fmaxf(m3, leaky(as.w + ad.w));
    }
#pragma unroll
    for (int off = 16; off; off >>= 1) {
        m0 = fmaxf(m0, __shfl_xor_sync(0xffffffffu, m0, off));
        m1 = fmaxf(m1, __shfl_xor_sync(0xffffffffu, m1, off));
        m2 = fmaxf(m2, __shfl_xor_sync(0xffffffffu, m2, off));
        m3 = fmaxf(m3, __shfl_xor_sync(0xffffffffu, m3, off));
    }
    float d0 = 0.f, d1 = 0.f, d2 = 0.f, d3 = 0.f;
    for (int i = b + lane; i < e; i += 32) {
        int s = g_srcs[i];
        float4 as = *(const float4*)(g_asrc + s * 4);
        float4 w;
        w.x = __expf(leaky(as.x + ad.x) - m0); d0 += w.x;
        w.y = __expf(leaky(as.y + ad.y) - m1); d1 += w.y;
        w.z = __expf(leaky(as.z + ad.z) - m2); d2 += w.z;
        w.w = __expf(leaky(as.w + ad.w) - m3); d3 += w.w;
        *(float4*)(g_ew + (size_t)i * 4) = w;
    }
#pragma unroll
    for (int off = 16; off; off >>= 1) {
        d0 += __shfl_xor_sync(0xffffffffu, d0, off);
        d1 += __shfl_xor_sync(0xffffffffu, d1, off);
        d2 += __shfl_xor_sync(0xffffffffu, d2, off);
        d3 += __shfl_xor_sync(0xffffffffu, d3, off);
    }
    if (lane == 0) {
        float4 dv = {d0, d1, d2, d3};
        *(float4*)(g_den + n * 4) = dv;
    }
}

// ---------------- aggregation: warp per node ----------------
__global__ void k_aggr(const float* __restrict__ cb) {
    int n = (blockIdx.x * blockDim.x + threadIdx.x) >> 5;
    if (n >= NN) return;
    int lane = threadIdx.x & 31;
    int b = g_rowptr[n], e = g_rowptr[n + 1];
    float4 den = *(const float4*)(g_den + n * 4);
    float i0 = 1.f / (den.x + 1e-16f);
    float i1 = 1.f / (den.y + 1e-16f);
    float i2 = 1.f / (den.z + 1e-16f);
    float i3 = 1.f / (den.w + 1e-16f);
    float4 a0 = {0, 0, 0, 0}, a1 = a0, a2 = a0, a3 = a0;
    for (int i = b; i < e; i++) {
        int s = g_srcs[i];
        float4 w = *(const float4*)(g_ew + (size_t)i * 4);
        const float4* hp = (const float4*)(g_h + (size_t)s * HD) + lane;
        float4 h0 = hp[0], h1 = hp[32], h2 = hp[64], h3 = hp[96];
        a0.x = fmaf(w.x, h0.x, a0.x); a0.y = fmaf(w.x, h0.y, a0.y);
        a0.z = fmaf(w.x, h0.z, a0.z); a0.w = fmaf(w.x, h0.w, a0.w);
        a1.x = fmaf(w.y, h1.x, a1.x); a1.y = fmaf(w.y, h1.y, a1.y);
        a1.z = fmaf(w.y, h1.z, a1.z); a1.w = fmaf(w.y, h1.w, a1.w);
        a2.x = fmaf(w.z, h2.x, a2.x); a2.y = fmaf(w.z, h2.y, a2.y);
        a2.z = fmaf(w.z, h2.z, a2.z); a2.w = fmaf(w.z, h2.w, a2.w);
        a3.x = fmaf(w.w, h3.x, a3.x); a3.y = fmaf(w.w, h3.y, a3.y);
        a3.z = fmaf(w.w, h3.z, a3.z); a3.w = fmaf(w.w, h3.w, a3.w);
    }
    float4 bias = *(const float4*)(cb + lane * 4);
    float4 o;
    o.x = 0.25f * (a0.x * i0 + a1.x * i1 + a2.x * i2 + a3.x * i3) + bias.x;
    o.y = 0.25f * (a0.y * i0 + a1.y * i1 + a2.y * i2 + a3.y * i3) + bias.y;
    o.z = 0.25f * (a0.z * i0 + a1.z * i1 + a2.z * i2 + a3.z * i3) + bias.z;
    o.w = 0.25f * (a0.w * i0 + a1.w * i1 + a2.w * i2 + a3.w * i3) + bias.w;
    *(float4*)(g_conv + (size_t)n * HID + lane * 4) = o;
}

// ---------------- host orchestration ----------------
extern "C" void kernel_launch(void* const* d_in, const int* in_sizes, int n_in,
                              void* d_out, int out_size) {
    const float* x       = (const float*)d_in[0];
    const void*  ei      = d_in[1];
    const float* conv_w  = (const float*)d_in[2];
    const float* att_src = (const float*)d_in[3];
    const float* att_dst = (const float*)d_in[4];
    const float* conv_b  = (const float*)d_in[5];
    const float* proj_w  = (const float*)d_in[6];
    const float* proj_b  = (const float*)d_in[7];
    const float* skip_w  = (const float*)d_in[8];
    const float* skip_b  = (const float*)d_in[9];
    float* out = (float*)d_out;

    float *p_h, *p_conv, *p_tmp, *p_asrc, *p_adst;
    __nv_bfloat16 *p_wth, *p_wtl;
    cudaGetSymbolAddress((void**)&p_h, g_h);
    cudaGetSymbolAddress((void**)&p_conv, g_conv);
    cudaGetSymbolAddress((void**)&p_tmp, g_tmp);
    cudaGetSymbolAddress((void**)&p_asrc, g_asrc);
    cudaGetSymbolAddress((void**)&p_adst, g_adst);
    cudaGetSymbolAddress((void**)&p_wth, g_wth);
    cudaGetSymbolAddress((void**)&p_wtl, g_wtl);

    cudaFuncSetAttribute(k_hmma<true, 1, false>, cudaFuncAttributeMaxDynamicSharedMemorySize, SM_TOT);
    cudaFuncSetAttribute(k_hmma<false, 2, true>, cudaFuncAttributeMaxDynamicSharedMemorySize, SM_TOT);

    // CSR build + weight split (once per call)
    k_detect<<<1, 256>>>((const unsigned int*)ei);
    k_zero_deg<<<NBLK, 256>>>();
    k_degree<<<(NE + 255) / 256, 256>>>(ei);
    k_scan1<<<NBLK, 256>>>();
    k_scan2<<<1, 256>>>();
    k_scan3<<<NBLK, 256>>>();
    k_bucket<<<(NE + 255) / 256, 256>>>(ei);
    k_wsplit<<<(2 * 768 * 128 + 255) / 256, 256>>>(conv_w, proj_w, skip_w);

    const float* feat = x;
    const int NWB = (NN + 7) / 8;     // warp-per-node blocks at 256 threads
    const int MT = (NN + 127) / 128;  // 391 M-tiles
    for (int l = 0; l < 2; l++) {
        float* lout = (l == 0) ? p_tmp : out;
        const __nv_bfloat16* wh = p_wth + (size_t)l * 98304;
        const __nv_bfloat16* wl = p_wtl + (size_t)l * 98304;
        // conv GEMM: h = feat @ conv_w, fused per-head attention logits
        dim3 gc(4, MT);
        k_hmma<true, 1, false><<<gc, 256, SM_TOT>>>(
            feat, nullptr, wh, wl, p_h, nullptr, nullptr, NN, HD,
            att_src + l * HD, att_dst + l * HD, p_asrc, p_adst);
        k_soft<<<NWB, 256>>>();
        k_aggr<<<NWB, 256>>>(conv_b + l * HID);
        // out = relu(conv) @ proj_w + proj_b + feat @ skip_w + skip_b   (fused K=256)
        dim3 gp(1, MT);
        k_hmma<false, 2, true><<<gp, 256, SM_TOT>>>(
            p_conv, feat, wh + 65536, wl + 65536, lout,
            proj_b + l * HID, skip_b + l * HID, NN, HID,
            nullptr, nullptr, nullptr, nullptr);
        feat = p_tmp;
    }
}

// round 9
// speedup vs baseline: 3.2358x; 1.2268x over previous
#include <cuda_runtime.h>
#include <cuda_bf16.h>
#include <cstdint>

#define NN 50000
#define NE 800000
#define HID 128
#define HEADS 4
#define HD 512  // HEADS*HID
#define NEG 0.2f
#define NBLK ((NN + 255) / 256)

// ---------------- scratch (device globals; no allocation allowed) ----------------
__device__ float g_aggx[(size_t)NN * HD];     // [N, H*128] per-head weighted x aggregation
__device__ float g_asrc[NN * HEADS];
__device__ float g_adst[NN * HEADS];
__device__ float g_den[NN * HEADS];
__device__ float g_ew[(size_t)NE * HEADS];    // per sorted edge, per head softmax numerator
__device__ float g_conv[(size_t)NN * HID];    // GAT layer output (head-mean + bias)
__device__ float g_tmp[(size_t)NN * HID];     // layer-0 output features
__device__ float g_va[2 * 2 * HEADS * HID];   // folded attention vectors [l][s/d][h][k]
__device__ int   g_rowptr[NN + 1];
__device__ int   g_deg[NN];
__device__ int   g_srcs[NE];
__device__ int   g_bsum[NBLK];
__device__ int   g_is64;
// transposed + bf16-split weights: per layer 768 rows (512 conv(*0.25) | 128 proj | 128 skip) x 128 k
__device__ __nv_bfloat16 g_wth[2 * 768 * 128];
__device__ __nv_bfloat16 g_wtl[2 * 768 * 128];

__device__ __forceinline__ uint32_t smem_u32(const void* p) {
    uint32_t a;
    asm("{ .reg .u64 t; cvta.to.shared.u64 t, %1; cvt.u32.u64 %0, t; }" : "=r"(a) : "l"(p));
    return a;
}

#define LDM_X4(r0, r1, r2, r3, addr) \
    asm volatile("ldmatrix.sync.aligned.m8n8.x4.shared.b16 {%0,%1,%2,%3}, [%4];" \
        : "=r"(r0), "=r"(r1), "=r"(r2), "=r"(r3) : "r"(addr))

#define MMA_BF16(c, a, b) \
    asm volatile("mma.sync.aligned.m16n8k16.row.col.f32.bf16.bf16.f32 " \
        "{%0,%1,%2,%3}, {%4,%5,%6,%7}, {%8,%9}, {%0,%1,%2,%3};" \
        : "+f"((c)[0]), "+f"((c)[1]), "+f"((c)[2]), "+f"((c)[3]) \
        : "r"((a)[0]), "r"((a)[1]), "r"((a)[2]), "r"((a)[3]), "r"((b)[0]), "r"((b)[1]))

// ---------------- edge dtype detection (int64 vs demoted int32) ----------------
__global__ void k_detect(const unsigned int* p) {
    __shared__ unsigned int acc;
    if (threadIdx.x == 0) acc = 0u;
    __syncthreads();
    unsigned int v = 0u;
    for (int i = threadIdx.x; i < 4096; i += 256) v |= p[2 * i + 1];
    atomicOr(&acc, v);
    __syncthreads();
    if (threadIdx.x == 0) g_is64 = (acc == 0u) ? 1 : 0;
}
__device__ __forceinline__ int edge_val(const void* ei, int idx) {
    if (g_is64) return (int)((const long long*)ei)[idx];
    return ((const int*)ei)[idx];
}

// ---------------- CSR build ----------------
__global__ void k_zero_deg() {
    int i = blockIdx.x * blockDim.x + threadIdx.x;
    if (i < NN) g_deg[i] = 0;
}
__global__ void k_degree(const void* ei) {
    int e = blockIdx.x * blockDim.x + threadIdx.x;
    if (e >= NE) return;
    atomicAdd(&g_deg[edge_val(ei, NE + e)], 1);
}
__device__ __forceinline__ int warp_incl_scan(int x, int lane) {
#pragma unroll
    for (int o = 1; o < 32; o <<= 1) {
        int y = __shfl_up_sync(0xffffffffu, x, o);
        if (lane >= o) x += y;
    }
    return x;
}
__global__ void k_scan1() {
    int b = blockIdx.x, t = threadIdx.x, i = b * 256 + t;
    int lane = t & 31, w = t >> 5;
    int v = (i < NN) ? g_deg[i] : 0;
    int x = warp_incl_scan(v, lane);
    __shared__ int ws[8];
    if (lane == 31) ws[w] = x;
    __syncthreads();
    int add = 0;
#pragma unroll
    for (int j = 0; j < 8; j++) if (j < w) add += ws[j];
    int incl = x + add;
    if (i < NN) g_rowptr[i] = incl - v;
    if (t == 255) g_bsum[b] = incl;
}
__global__ void k_scan2() {
    int t = threadIdx.x, lane = t & 31, w = t >> 5;
    int v = (t < NBLK) ? g_bsum[t] : 0;
    int x = warp_incl_scan(v, lane);
    __shared__ int ws[8];
    if (lane == 31) ws[w] = x;
    __syncthreads();
    int add = 0;
#pragma unroll
    for (int j = 0; j < 8; j++) if (j < w) add += ws[j];
    if (t < NBLK) g_bsum[t] = x + add - v;
}
__global__ void k_scan3() {
    int i = blockIdx.x * blockDim.x + threadIdx.x;
    if (i < NN) { g_rowptr[i] += g_bsum[i >> 8]; g_deg[i] = 0; }
    if (i == 0) g_rowptr[NN] = NE;
}
__global__ void k_bucket(const void* ei) {
    int e = blockIdx.x * blockDim.x + threadIdx.x;
    if (e >= NE) return;
    int s = edge_val(ei, e);
    int d = edge_val(ei, NE + e);
    int pos = atomicAdd(&g_deg[d], 1);
    g_srcs[g_rowptr[d] + pos] = s;
}

// ---------------- weight transpose + bf16 hi/lo split ----------------
__global__ void k_wsplit(const float* __restrict__ conv_w, const float* __restrict__ proj_w,
                         const float* __restrict__ skip_w) {
    int i = blockIdx.x * 256 + threadIdx.x;
    if (i >= 2 * 768 * 128) return;
    int l = i / 98304, r = i % 98304;
    int row = r >> 7, k = r & 127;
    float v;
    if (row < 512)       v = conv_w[l * 65536 + k * 512 + row] * 0.25f;  // fold head-mean
    else if (row < 640)  v = proj_w[l * 16384 + k * 128 + (row - 512)];
    else                 v = skip_w[l * 16384 + k * 128 + (row - 640)];
    __nv_bfloat16 hi = __float2bfloat16(v);
    __nv_bfloat16 lo = __float2bfloat16(v - __bfloat162float(hi));
    g_wth[i] = hi;
    g_wtl[i] = lo;
}

// ---------------- folded attention vectors: va[l][sd][h][k] = sum_c W[k, h*128+c]*a[h,c] ----------------
__global__ void k_valpha(const float* __restrict__ conv_w, const float* __restrict__ att_src,
                         const float* __restrict__ att_dst) {
    int idx = blockIdx.x * 256 + threadIdx.x;   // 2048 outputs
    if (idx >= 2048) return;
    int l = idx >> 10, r = idx & 1023;
    int sd = r >> 9, h = (r >> 7) & 3, k = r & 127;
    const float* w = conv_w + l * 65536 + k * 512 + h * 128;
    const float* a = (sd ? att_dst : att_src) + l * 512 + h * 128;
    float s = 0.f;
#pragma unroll
    for (int c = 0; c < 128; c += 4) {
        float4 wv = *(const float4*)(w + c);
        float4 av = *(const float4*)(a + c);
        s += wv.x * av.x + wv.y * av.y + wv.z * av.z + wv.w * av.w;
    }
    g_va[idx] = s;
}

// ---------------- attention logits from feat directly: warp per node ----------------
__global__ void k_alpha_x(const float* __restrict__ feat, const float* __restrict__ va) {
    int n = (blockIdx.x * blockDim.x + threadIdx.x) >> 5;
    if (n >= NN) return;
    int lane = threadIdx.x & 31;
    float4 xv = *(const float4*)(feat + (size_t)n * HID + lane * 4);
#pragma unroll
    for (int h = 0; h < HEADS; h++) {
        float4 s4 = *(const float4*)(va + h * 128 + lane * 4);
        float4 d4 = *(const float4*)(va + 512 + h * 128 + lane * 4);
        float s1 = xv.x * s4.x + xv.y * s4.y + xv.z * s4.z + xv.w * s4.w;
        float s2 = xv.x * d4.x + xv.y * d4.y + xv.z * d4.z + xv.w * d4.w;
#pragma unroll
        for (int off = 16; off; off >>= 1) {
            s1 += __shfl_xor_sync(0xffffffffu, s1, off);
            s2 += __shfl_xor_sync(0xffffffffu, s2, off);
        }
        if (lane == 0) {
            g_asrc[n * HEADS + h] = s1;
            g_adst[n * HEADS + h] = s2;
        }
    }
}

__device__ __forceinline__ float leaky(float a) { return a >= 0.f ? a : NEG * a; }

// ---------------- per-node softmax: max, exp weights, denom (warp per node) ----------------
__global__ void k_soft() {
    int n = (blockIdx.x * blockDim.x + threadIdx.x) >> 5;
    if (n >= NN) return;
    int lane = threadIdx.x & 31;
    int b = g_rowptr[n], e = g_rowptr[n + 1];
    float4 ad = *(const float4*)(g_adst + n * 4);
    float m0 = -3.4e38f, m1 = m0, m2 = m0, m3 = m0;
    for (int i = b + lane; i < e; i += 32) {
        int s = g_srcs[i];
        float4 as = *(const float4*)(g_asrc + s * 4);
        m0 = fmaxf(m0, leaky(as.x + ad.x));
        m1 = fmaxf(m1, leaky(as.y + ad.y));
        m2 = fmaxf(m2, leaky(as.z + ad.z));
        m3 = fmaxf(m3, leaky(as.w + ad.w));
    }
#pragma unroll
    for (int off = 16; off; off >>= 1) {
        m0 = fmaxf(m0, __shfl_xor_sync(0xffffffffu, m0, off));
        m1 = fmaxf(m1, __shfl_xor_sync(0xffffffffu, m1, off));
        m2 = fmaxf(m2, __shfl_xor_sync(0xffffffffu, m2, off));
        m3 = fmaxf(m3, __shfl_xor_sync(0xffffffffu, m3, off));
    }
    float d0 = 0.f, d1 = 0.f, d2 = 0.f, d3 = 0.f;
    for (int i = b + lane; i < e; i += 32) {
        int s = g_srcs[i];
        float4 as = *(const float4*)(g_asrc + s * 4);
        float4 w;
        w.x = __expf(leaky(as.x + ad.x) - m0); d0 += w.x;
        w.y = __expf(leaky(as.y + ad.y) - m1); d1 += w.y;
        w.z = __expf(leaky(as.z + ad.z) - m2); d2 += w.z;
        w.w = __expf(leaky(as.w + ad.w) - m3); d3 += w.w;
        *(float4*)(g_ew + (size_t)i * 4) = w;
    }
#pragma unroll
    for (int off = 16; off; off >>= 1) {
        d0 += __shfl_xor_sync(0xffffffffu, d0, off);
        d1 += __shfl_xor_sync(0xffffffffu, d1, off);
        d2 += __shfl_xor_sync(0xffffffffu, d2, off);
        d3 += __shfl_xor_sync(0xffffffffu, d3, off);
    }
    if (lane == 0) {
        float4 dv = {d0, d1, d2, d3};
        *(float4*)(g_den + n * 4) = dv;
    }
}

// ---------------- x-space aggregation: warp per node, 4 head accumulators over x rows ----------------
__global__ void k_aggr_x(const float* __restrict__ feat) {
    int n = (blockIdx.x * blockDim.x + threadIdx.x) >> 5;
    if (n >= NN) return;
    int lane = threadIdx.x & 31;
    int b = g_rowptr[n], e = g_rowptr[n + 1];
    float4 den = *(const float4*)(g_den + n * 4);
    float i0 = 1.f / (den.x + 1e-16f);
    float i1 = 1.f / (den.y + 1e-16f);
    float i2 = 1.f / (den.z + 1e-16f);
    float i3 = 1.f / (den.w + 1e-16f);
    float4 a0 = {0, 0, 0, 0}, a1 = a0, a2 = a0, a3 = a0;
    for (int i = b; i < e; i++) {
        int s = g_srcs[i];                                  // warp-uniform
        float4 w = *(const float4*)(g_ew + (size_t)i * 4);  // warp-uniform
        float4 xv = *(const float4*)(feat + (size_t)s * HID + lane * 4);
        a0.x = fmaf(w.x, xv.x, a0.x); a0.y = fmaf(w.x, xv.y, a0.y);
        a0.z = fmaf(w.x, xv.z, a0.z); a0.w = fmaf(w.x, xv.w, a0.w);
        a1.x = fmaf(w.y, xv.x, a1.x); a1.y = fmaf(w.y, xv.y, a1.y);
        a1.z = fmaf(w.y, xv.z, a1.z); a1.w = fmaf(w.y, xv.w, a1.w);
        a2.x = fmaf(w.z, xv.x, a2.x); a2.y = fmaf(w.z, xv.y, a2.y);
        a2.z = fmaf(w.z, xv.z, a2.z); a2.w = fmaf(w.z, xv.w, a2.w);
        a3.x = fmaf(w.w, xv.x, a3.x); a3.y = fmaf(w.w, xv.y, a3.y);
        a3.z = fmaf(w.w, xv.z, a3.z); a3.w = fmaf(w.w, xv.w, a3.w);
    }
    float* arow = g_aggx + (size_t)n * HD + lane * 4;
    float4 o0 = {a0.x * i0, a0.y * i0, a0.z * i0, a0.w * i0};
    float4 o1 = {a1.x * i1, a1.y * i1, a1.z * i1, a1.w * i1};
    float4 o2 = {a2.x * i2, a2.y * i2, a2.z * i2, a2.w * i2};
    float4 o3 = {a3.x * i3, a3.y * i3, a3.z * i3, a3.w * i3};
    *(float4*)(arow)       = o0;
    *(float4*)(arow + 128) = o1;
    *(float4*)(arow + 256) = o2;
    *(float4*)(arow + 384) = o3;
}

// ================= HMMA split-bf16 GEMM =================
#define TILE_STRIDE 272            // (128+8) bf16 per row
#define TILE_BYTES  (128 * TILE_STRIDE)
#define SM_BIAS 0
#define SM_TILE 1024
#define SM_TOT  (SM_TILE + 4 * TILE_BYTES)   // 140288 B

__device__ __forceinline__ uint32_t pack_bf2(__nv_bfloat16 a, __nv_bfloat16 b) {
    return (uint32_t)__bfloat16_as_ushort(a) | ((uint32_t)__bfloat16_as_ushort(b) << 16);
}

// NCHUNK k-chunks of 128. STRIDEK: chunks are k-slices of A0 (lda=512);
// else chunk0=A0, chunk1=A1 (lda=128). RELU0: relu on chunk-0 A operand.
template <int NCHUNK, bool STRIDEK, bool RELU0>
__global__ __launch_bounds__(256, 1) void k_hmma(
    const float* __restrict__ A0, const float* __restrict__ A1, int lda,
    const __nv_bfloat16* __restrict__ Bh, const __nv_bfloat16* __restrict__ Bl,
    float* __restrict__ C, const float* __restrict__ bias, const float* __restrict__ bias2,
    int M, int ldc)
{
    extern __shared__ char sm[];
    uint32_t smb = smem_u32(sm);
    const uint32_t uAh = smb + SM_TILE;
    const uint32_t uAl = uAh + TILE_BYTES;
    const uint32_t uBh = uAl + TILE_BYTES;
    const uint32_t uBl = uBh + TILE_BYTES;
    float* sBias = (float*)(sm + SM_BIAS);

    int t = threadIdx.x, lane = t & 31, wid = t >> 5;
    int bm = blockIdx.y * 128;

    if (t < 128) {
        float bv = bias ? bias[t] : 0.f;
        if (bias2) bv += bias2[t];
        sBias[t] = bv;
    }

    int wm = (wid >> 2) * 64, wn = (wid & 3) * 32;
    const uint32_t aOff = (uint32_t)((wm + (lane & 7) + (lane & 8)) * TILE_STRIDE + ((lane & 16) ? 16 : 0));
    const uint32_t bOff = (uint32_t)((wn + (lane & 7) + ((lane & 16) ? 8 : 0)) * TILE_STRIDE + ((lane & 8) ? 16 : 0));

    float c[4][4][4];
#pragma unroll
    for (int i = 0; i < 4; i++)
#pragma unroll
        for (int j = 0; j < 4; j++)
#pragma unroll
            for (int k = 0; k < 4; k++) c[i][j][k] = 0.f;

#pragma unroll
    for (int ch = 0; ch < NCHUNK; ch++) {
        const float* Asrc = STRIDEK ? (A0 + ch * 128) : (ch == 0 ? A0 : A1);
        const bool relu = RELU0 && (ch == 0);
        // ---- A: fp32 -> bf16 hi/lo split into smem ----
#pragma unroll
        for (int i = 0; i < 8; i++) {
            int idx = t + i * 256;
            int r = idx >> 4, kc = idx & 15;
            int m = bm + r;
            float4 v0, v1;
            if (m < M) {
                const float4* p = (const float4*)(Asrc + (size_t)m * lda + kc * 8);
                v0 = p[0]; v1 = p[1];
            } else {
                v0 = make_float4(0.f, 0.f, 0.f, 0.f); v1 = v0;
            }
            float f[8] = {v0.x, v0.y, v0.z, v0.w, v1.x, v1.y, v1.z, v1.w};
            if (relu) {
#pragma unroll
                for (int j = 0; j < 8; j++) f[j] = fmaxf(f[j], 0.f);
            }
            uint4 uh, ul;
            uint32_t* ph = (uint32_t*)&uh;
            uint32_t* pl = (uint32_t*)&ul;
#pragma unroll
            for (int j = 0; j < 4; j++) {
                float a = f[2 * j], b = f[2 * j + 1];
                __nv_bfloat16 ha = __float2bfloat16(a), hb = __float2bfloat16(b);
                __nv_bfloat16 la = __float2bfloat16(a - __bfloat162float(ha));
                __nv_bfloat16 lb = __float2bfloat16(b - __bfloat162float(hb));
                ph[j] = pack_bf2(ha, hb);
                pl[j] = pack_bf2(la, lb);
            }
            uint32_t off = (uint32_t)(r * TILE_STRIDE + kc * 16);
            *(uint4*)(sm + SM_TILE + off) = uh;
            *(uint4*)(sm + SM_TILE + TILE_BYTES + off) = ul;
        }
        // ---- B: bf16 hi/lo copy into smem ----
        {
            const __nv_bfloat16* bh = Bh + (size_t)ch * 16384;
            const __nv_bfloat16* bl = Bl + (size_t)ch * 16384;
#pragma unroll
            for (int i = 0; i < 8; i++) {
                int idx = t + i * 256;
                int r = idx >> 4, kc = idx & 15;
                uint4 vh = *(const uint4*)(bh + r * 128 + kc * 8);
                uint4 vl = *(const uint4*)(bl + r * 128 + kc * 8);
                uint32_t off = (uint32_t)(r * TILE_STRIDE + kc * 16);
                *(uint4*)(sm + SM_TILE + 2 * TILE_BYTES + off) = vh;
                *(uint4*)(sm + SM_TILE + 3 * TILE_BYTES + off) = vl;
            }
        }
        __syncthreads();

        // ---- 3 precision passes: Ah*Bh, Ah*Bl, Al*Bh ----
#pragma unroll
        for (int pass = 0; pass < 3; pass++) {
            uint32_t aBase = ((pass == 2) ? uAl : uAh) + aOff;
            uint32_t bBase = ((pass == 1) ? uBl : uBh) + bOff;
#pragma unroll
            for (int k0 = 0; k0 < 8; k0++) {
                uint32_t ka = aBase + k0 * 32;
                uint32_t kb = bBase + k0 * 32;
                uint32_t a[4][4], b[4][2];
#pragma unroll
                for (int mt = 0; mt < 4; mt++)
                    LDM_X4(a[mt][0], a[mt][1], a[mt][2], a[mt][3], ka + mt * 16 * TILE_STRIDE);
#pragma unroll
                for (int np = 0; np < 2; np++)
                    LDM_X4(b[2 * np][0], b[2 * np][1], b[2 * np + 1][0], b[2 * np + 1][1],
                           kb + np * 16 * TILE_STRIDE);
#pragma unroll
                for (int mt = 0; mt < 4; mt++)
#pragma unroll
                    for (int nt = 0; nt < 4; nt++)
                        MMA_BF16(c[mt][nt], a[mt], b[nt]);
            }
        }
        if (ch + 1 < NCHUNK) __syncthreads();  // protect smem reuse on next chunk
    }

    // ---- epilogue ----
    int g = lane >> 2, t2 = (lane & 3) * 2;
#pragma unroll
    for (int mt = 0; mt < 4; mt++) {
        int r0 = wm + mt * 16 + g;
        int m0 = bm + r0, m1 = m0 + 8;
#pragma unroll
        for (int nt = 0; nt < 4; nt++) {
            int col = wn + nt * 8 + t2;
            float bb0 = sBias[col], bb1 = sBias[col + 1];
            if (m0 < M) {
                float2 o = {c[mt][nt][0] + bb0, c[mt][nt][1] + bb1};
                *(float2*)(C + (size_t)m0 * ldc + col) = o;
            }
            if (m1 < M) {
                float2 o = {c[mt][nt][2] + bb0, c[mt][nt][3] + bb1};
                *(float2*)(C + (size_t)m1 * ldc + col) = o;
            }
        }
    }
}

// ---------------- host orchestration ----------------
extern "C" void kernel_launch(void* const* d_in, const int* in_sizes, int n_in,
                              void* d_out, int out_size) {
    const float* x       = (const float*)d_in[0];
    const void*  ei      = d_in[1];
    const float* conv_w  = (const float*)d_in[2];
    const float* att_src = (const float*)d_in[3];
    const float* att_dst = (const float*)d_in[4];
    const float* conv_b  = (const float*)d_in[5];
    const float* proj_w  = (const float*)d_in[6];
    const float* proj_b  = (const float*)d_in[7];
    const float* skip_w  = (const float*)d_in[8];
    const float* skip_b  = (const float*)d_in[9];
    float* out = (float*)d_out;

    float *p_aggx, *p_conv, *p_tmp, *p_va;
    __nv_bfloat16 *p_wth, *p_wtl;
    cudaGetSymbolAddress((void**)&p_aggx, g_aggx);
    cudaGetSymbolAddress((void**)&p_conv, g_conv);
    cudaGetSymbolAddress((void**)&p_tmp, g_tmp);
    cudaGetSymbolAddress((void**)&p_va, g_va);
    cudaGetSymbolAddress((void**)&p_wth, g_wth);
    cudaGetSymbolAddress((void**)&p_wtl, g_wtl);

    cudaFuncSetAttribute(k_hmma<4, true, false>, cudaFuncAttributeMaxDynamicSharedMemorySize, SM_TOT);
    cudaFuncSetAttribute(k_hmma<2, false, true>, cudaFuncAttributeMaxDynamicSharedMemorySize, SM_TOT);

    // CSR build + weight prep (once per call)
    k_detect<<<1, 256>>>((const unsigned int*)ei);
    k_zero_deg<<<NBLK, 256>>>();
    k_degree<<<(NE + 255) / 256, 256>>>(ei);
    k_scan1<<<NBLK, 256>>>();
    k_scan2<<<1, 256>>>();
    k_scan3<<<NBLK, 256>>>();
    k_bucket<<<(NE + 255) / 256, 256>>>(ei);
    k_wsplit<<<(2 * 768 * 128 + 255) / 256, 256>>>(conv_w, proj_w, skip_w);
    k_valpha<<<8, 256>>>(conv_w, att_src, att_dst);

    const float* feat = x;
    const int NWB = (NN + 7) / 8;     // warp-per-node blocks at 256 threads
    const int MT = (NN + 127) / 128;  // 391 M-tiles
    for (int l = 0; l < 2; l++) {
        float* lout = (l == 0) ? p_tmp : out;
        const __nv_bfloat16* wh = p_wth + (size_t)l * 98304;
        const __nv_bfloat16* wl = p_wtl + (size_t)l * 98304;
        // attention logits directly from feat (folded vectors)
        k_alpha_x<<<NWB, 256>>>(feat, p_va + l * 1024);
        k_soft<<<NWB, 256>>>();
        // x-space aggregation (normalized, per head)
        k_aggr_x<<<NWB, 256>>>(feat);
        // conv = aggx @ (0.25 * Wstack) + conv_b   (K=512, 4 chunks)
        dim3 gc(1, MT);
        k_hmma<4, true, false><<<gc, 256, SM_TOT>>>(
            p_aggx, nullptr, HD, wh, wl, p_conv, conv_b + l * HID, nullptr, NN, HID);
        // out = relu(conv) @ proj_w + proj_b + feat @ skip_w + skip_b   (fused K=256)
        k_hmma<2, false, true><<<gc, 256, SM_TOT>>>(
            p_conv, feat, HID, wh + 65536, wl + 65536, lout,
            proj_b + l * HID, skip_b + l * HID, NN, HID);
        feat = p_tmp;
    }
}